// round 1
// baseline (speedup 1.0000x reference)
#include <cuda_runtime.h>
#include <math.h>

#define S_LEN 2048
#define D_MODEL 2048
#define N_H 16
#define N_KV 4
#define H_DIM 128
#define SCALING 0.08838834764831845f
#define DM0 0.9779029130879204f

// Scratch (allocation-free rule: __device__ globals)
__device__ float g_q[(size_t)S_LEN * N_H * H_DIM];
__device__ float g_k[(size_t)S_LEN * N_KV * H_DIM];
__device__ float g_v[(size_t)S_LEN * N_KV * H_DIM];
__device__ float g_ctx[(size_t)S_LEN * N_H * H_DIM];
__device__ float g_attn[(size_t)N_H * S_LEN * S_LEN];  // fallback if d_out holds only `out`

// ---------------------------------------------------------------------------
// Generic NT GEMM: C[M,N] = A[M,K] * B[N,K]^T   (row-major A, B)
// BM=BN=128, BK=16, 256 threads, 8x8 micro-tile per thread.
// M,N multiples of 128; K multiple of 16.
// ---------------------------------------------------------------------------
__global__ void __launch_bounds__(256) gemm_nt_kernel(
    const float* __restrict__ A, const float* __restrict__ B,
    float* __restrict__ C, int M, int N, int K)
{
    __shared__ float As[16][128];
    __shared__ float Bs[16][128];

    const int tid = threadIdx.x;
    const int tx  = tid & 15;        // n micro-group
    const int ty  = tid >> 4;        // m micro-group
    const int mBase = blockIdx.y * 128;
    const int nBase = blockIdx.x * 128;

    const int lr = tid >> 1;         // 0..127 row within tile
    const int lc = (tid & 1) * 8;    // 0 or 8  col within k-slab

    const float* Ap = A + (size_t)(mBase + lr) * K + lc;
    const float* Bp = B + (size_t)(nBase + lr) * K + lc;

    float acc[8][8];
#pragma unroll
    for (int i = 0; i < 8; i++)
#pragma unroll
        for (int j = 0; j < 8; j++) acc[i][j] = 0.f;

    for (int k0 = 0; k0 < K; k0 += 16) {
        float4 a0 = *(const float4*)(Ap + k0);
        float4 a1 = *(const float4*)(Ap + k0 + 4);
        float4 b0 = *(const float4*)(Bp + k0);
        float4 b1 = *(const float4*)(Bp + k0 + 4);
        __syncthreads();
        As[lc + 0][lr] = a0.x; As[lc + 1][lr] = a0.y; As[lc + 2][lr] = a0.z; As[lc + 3][lr] = a0.w;
        As[lc + 4][lr] = a1.x; As[lc + 5][lr] = a1.y; As[lc + 6][lr] = a1.z; As[lc + 7][lr] = a1.w;
        Bs[lc + 0][lr] = b0.x; Bs[lc + 1][lr] = b0.y; Bs[lc + 2][lr] = b0.z; Bs[lc + 3][lr] = b0.w;
        Bs[lc + 4][lr] = b1.x; Bs[lc + 5][lr] = b1.y; Bs[lc + 6][lr] = b1.z; Bs[lc + 7][lr] = b1.w;
        __syncthreads();
#pragma unroll
        for (int kk = 0; kk < 16; kk++) {
            float a[8], b[8];
            *(float4*)&a[0] = *(const float4*)&As[kk][ty * 8];
            *(float4*)&a[4] = *(const float4*)&As[kk][ty * 8 + 4];
            *(float4*)&b[0] = *(const float4*)&Bs[kk][tx * 8];
            *(float4*)&b[4] = *(const float4*)&Bs[kk][tx * 8 + 4];
#pragma unroll
            for (int i = 0; i < 8; i++)
#pragma unroll
                for (int j = 0; j < 8; j++)
                    acc[i][j] = fmaf(a[i], b[j], acc[i][j]);
        }
    }

#pragma unroll
    for (int i = 0; i < 8; i++) {
        float* Cr = C + (size_t)(mBase + ty * 8 + i) * N + nBase + tx * 8;
        *(float4*)(Cr + 0) = make_float4(acc[i][0], acc[i][1], acc[i][2], acc[i][3]);
        *(float4*)(Cr + 4) = make_float4(acc[i][4], acc[i][5], acc[i][6], acc[i][7]);
    }
}

// ---------------------------------------------------------------------------
// RoPE (in place): X layout [S][nHeads][HD]. Each thread handles pair (d, d+64).
// ---------------------------------------------------------------------------
__global__ void rope_kernel(float* __restrict__ X,
                            const float* __restrict__ cosb,
                            const float* __restrict__ sinb, int nHeads)
{
    int idx = blockIdx.x * blockDim.x + threadIdx.x;
    int total = S_LEN * nHeads * (H_DIM / 2);
    if (idx >= total) return;
    int d = idx & 63;
    int t = idx >> 6;
    int hh = t % nHeads;
    int s  = t / nHeads;
    float c1 = cosb[s * H_DIM + d];
    float s1 = sinb[s * H_DIM + d];
    float c2 = cosb[s * H_DIM + d + 64];
    float s2 = sinb[s * H_DIM + d + 64];
    size_t base = (size_t)s * nHeads * H_DIM + (size_t)hh * H_DIM + d;
    float x1 = X[base];
    float x2 = X[base + 64];
    X[base]      = x1 * c1 - x2 * s1;
    X[base + 64] = x2 * c2 + x1 * s2;
}

// ---------------------------------------------------------------------------
// Scores: attn[h][m][n] = SCALING * dot(q[m,h,:], k[n,h/4,:]),  n-tile <= m-tile only
// ---------------------------------------------------------------------------
__global__ void __launch_bounds__(256) scores_kernel(float* __restrict__ attn)
{
    const int h = blockIdx.z;
    const int mBase = blockIdx.y * 128;
    const int nBase = blockIdx.x * 128;
    if (nBase > mBase + 127) return;   // fully above diagonal: entmax writes zeros there

    __shared__ float As[16][128];
    __shared__ float Bs[16][128];

    const int tid = threadIdx.x;
    const int tx  = tid & 15;
    const int ty  = tid >> 4;
    const int lr  = tid >> 1;
    const int lc  = (tid & 1) * 8;

    const float* Ap = g_q + (size_t)(mBase + lr) * (N_H * H_DIM) + h * H_DIM + lc;
    const float* Bp = g_k + (size_t)(nBase + lr) * (N_KV * H_DIM) + (h >> 2) * H_DIM + lc;

    float acc[8][8];
#pragma unroll
    for (int i = 0; i < 8; i++)
#pragma unroll
        for (int j = 0; j < 8; j++) acc[i][j] = 0.f;

#pragma unroll
    for (int k0 = 0; k0 < H_DIM; k0 += 16) {
        float4 a0 = *(const float4*)(Ap + k0);
        float4 a1 = *(const float4*)(Ap + k0 + 4);
        float4 b0 = *(const float4*)(Bp + k0);
        float4 b1 = *(const float4*)(Bp + k0 + 4);
        __syncthreads();
        As[lc + 0][lr] = a0.x; As[lc + 1][lr] = a0.y; As[lc + 2][lr] = a0.z; As[lc + 3][lr] = a0.w;
        As[lc + 4][lr] = a1.x; As[lc + 5][lr] = a1.y; As[lc + 6][lr] = a1.z; As[lc + 7][lr] = a1.w;
        Bs[lc + 0][lr] = b0.x; Bs[lc + 1][lr] = b0.y; Bs[lc + 2][lr] = b0.z; Bs[lc + 3][lr] = b0.w;
        Bs[lc + 4][lr] = b1.x; Bs[lc + 5][lr] = b1.y; Bs[lc + 6][lr] = b1.z; Bs[lc + 7][lr] = b1.w;
        __syncthreads();
#pragma unroll
        for (int kk = 0; kk < 16; kk++) {
            float a[8], b[8];
            *(float4*)&a[0] = *(const float4*)&As[kk][ty * 8];
            *(float4*)&a[4] = *(const float4*)&As[kk][ty * 8 + 4];
            *(float4*)&b[0] = *(const float4*)&Bs[kk][tx * 8];
            *(float4*)&b[4] = *(const float4*)&Bs[kk][tx * 8 + 4];
#pragma unroll
            for (int i = 0; i < 8; i++)
#pragma unroll
                for (int j = 0; j < 8; j++)
                    acc[i][j] = fmaf(a[i], b[j], acc[i][j]);
        }
    }

    float* base = attn + (size_t)h * S_LEN * S_LEN;
#pragma unroll
    for (int i = 0; i < 8; i++) {
        float* Cr = base + (size_t)(mBase + ty * 8 + i) * S_LEN + nBase + tx * 8;
        *(float4*)(Cr + 0) = make_float4(acc[i][0] * SCALING, acc[i][1] * SCALING,
                                         acc[i][2] * SCALING, acc[i][3] * SCALING);
        *(float4*)(Cr + 4) = make_float4(acc[i][4] * SCALING, acc[i][5] * SCALING,
                                         acc[i][6] * SCALING, acc[i][7] * SCALING);
    }
}

// ---------------------------------------------------------------------------
// Block reductions (256 threads)
// ---------------------------------------------------------------------------
__device__ __forceinline__ float block_reduce_sum(float v, float* sm)
{
#pragma unroll
    for (int o = 16; o > 0; o >>= 1) v += __shfl_down_sync(0xffffffffu, v, o);
    const int lane = threadIdx.x & 31, wid = threadIdx.x >> 5;
    __syncthreads();
    if (lane == 0) sm[wid] = v;
    __syncthreads();
    if (wid == 0) {
        v = (lane < 8) ? sm[lane] : 0.f;
#pragma unroll
        for (int o = 4; o > 0; o >>= 1) v += __shfl_down_sync(0xffffffffu, v, o);
        if (lane == 0) sm[8] = v;
    }
    __syncthreads();
    return sm[8];
}

__device__ __forceinline__ float block_reduce_max(float v, float* sm)
{
#pragma unroll
    for (int o = 16; o > 0; o >>= 1) v = fmaxf(v, __shfl_down_sync(0xffffffffu, v, o));
    const int lane = threadIdx.x & 31, wid = threadIdx.x >> 5;
    __syncthreads();
    if (lane == 0) sm[wid] = v;
    __syncthreads();
    if (wid == 0) {
        v = (lane < 8) ? sm[lane] : -INFINITY;
#pragma unroll
        for (int o = 4; o > 0; o >>= 1) v = fmaxf(v, __shfl_down_sync(0xffffffffu, v, o));
        if (lane == 0) sm[8] = v;
    }
    __syncthreads();
    return sm[8];
}

// ---------------------------------------------------------------------------
// alpha-entmax (alpha=1.5 -> p = relu(0.5*x - tau)^2), 50-iter bisection.
// One block (256 thr) per (head, query-row). In place on attn; zeros masked tail.
// Matches reference: d = S_LEN (full width) in the tau_hi constant.
// ---------------------------------------------------------------------------
__global__ void __launch_bounds__(256) entmax_kernel(float* __restrict__ attn)
{
    __shared__ float sm[9];
    const int row = blockIdx.x;
    const int h = row >> 11;          // / 2048
    const int q = row & 2047;
    float* x = attn + (size_t)h * S_LEN * S_LEN + (size_t)q * S_LEN;
    const int n = q + 1;
    const int tid = threadIdx.x;

    float X[8];
    float lmax = -INFINITY;
#pragma unroll
    for (int i = 0; i < 8; i++) {
        int j = tid + i * 256;
        if (j < n) {
            float v = x[j] * 0.5f;    // X = x * (alpha-1)
            X[i] = v;
            lmax = fmaxf(lmax, v);
        } else {
            X[i] = -INFINITY;
        }
    }
    float maxv = block_reduce_max(lmax, sm);

    float tau_lo = maxv - 1.0f;
    float dm = DM0;
    float tau_m = tau_lo;
#pragma unroll 1
    for (int it = 0; it < 50; it++) {
        dm *= 0.5f;
        tau_m = tau_lo + dm;
        float ls = 0.f;
#pragma unroll
        for (int i = 0; i < 8; i++) {
            float t = fmaxf(X[i] - tau_m, 0.f);
            ls = fmaf(t, t, ls);
        }
        float f = block_reduce_sum(ls, sm);
        if (f >= 1.0f) tau_lo = tau_m;
    }

    float p[8];
    float ls = 0.f;
#pragma unroll
    for (int i = 0; i < 8; i++) {
        float t = fmaxf(X[i] - tau_m, 0.f);
        p[i] = t * t;
        ls += p[i];
    }
    float s = block_reduce_sum(ls, sm);
    float inv = 1.0f / s;
#pragma unroll
    for (int i = 0; i < 8; i++) {
        int j = tid + i * 256;
        x[j] = (j < n) ? p[i] * inv : 0.0f;
    }
}

// ---------------------------------------------------------------------------
// ctx[m, h*128 + n] = sum_k attn[h][m][k] * v[k, (h/4)*128 + n]   (NN GEMM, causal K-range)
// BM=128, BN=128(=HD), BK=16
// ---------------------------------------------------------------------------
__global__ void __launch_bounds__(256) av_kernel(const float* __restrict__ attn)
{
    const int h = blockIdx.z;
    const int mBase = blockIdx.y * 128;

    __shared__ float As[16][128];
    __shared__ float Bs[16][128];

    const int tid = threadIdx.x;
    const int tx  = tid & 15;
    const int ty  = tid >> 4;

    const float* A = attn + (size_t)h * S_LEN * S_LEN;
    const float* B = g_v + (h >> 2) * H_DIM;

    const int lrA = tid >> 1;         // m row 0..127
    const int lcA = (tid & 1) * 8;    // k col 0 or 8
    const int krB = tid >> 4;         // k row 0..15
    const int ncB = (tid & 15) * 8;   // n col

    float acc[8][8];
#pragma unroll
    for (int i = 0; i < 8; i++)
#pragma unroll
        for (int j = 0; j < 8; j++) acc[i][j] = 0.f;

    const int kmax = mBase + 128;     // causal: attn is zero beyond the diagonal block
    for (int k0 = 0; k0 < kmax; k0 += 16) {
        float4 a0 = *(const float4*)(A + (size_t)(mBase + lrA) * S_LEN + k0 + lcA);
        float4 a1 = *(const float4*)(A + (size_t)(mBase + lrA) * S_LEN + k0 + lcA + 4);
        float4 b0 = *(const float4*)(B + (size_t)(k0 + krB) * (N_KV * H_DIM) + ncB);
        float4 b1 = *(const float4*)(B + (size_t)(k0 + krB) * (N_KV * H_DIM) + ncB + 4);
        __syncthreads();
        As[lcA + 0][lrA] = a0.x; As[lcA + 1][lrA] = a0.y; As[lcA + 2][lrA] = a0.z; As[lcA + 3][lrA] = a0.w;
        As[lcA + 4][lrA] = a1.x; As[lcA + 5][lrA] = a1.y; As[lcA + 6][lrA] = a1.z; As[lcA + 7][lrA] = a1.w;
        *(float4*)&Bs[krB][ncB]     = b0;
        *(float4*)&Bs[krB][ncB + 4] = b1;
        __syncthreads();
#pragma unroll
        for (int kk = 0; kk < 16; kk++) {
            float a[8], b[8];
            *(float4*)&a[0] = *(const float4*)&As[kk][ty * 8];
            *(float4*)&a[4] = *(const float4*)&As[kk][ty * 8 + 4];
            *(float4*)&b[0] = *(const float4*)&Bs[kk][tx * 8];
            *(float4*)&b[4] = *(const float4*)&Bs[kk][tx * 8 + 4];
#pragma unroll
            for (int i = 0; i < 8; i++)
#pragma unroll
                for (int j = 0; j < 8; j++)
                    acc[i][j] = fmaf(a[i], b[j], acc[i][j]);
        }
    }

#pragma unroll
    for (int i = 0; i < 8; i++) {
        float* Cr = g_ctx + (size_t)(mBase + ty * 8 + i) * (N_H * H_DIM) + h * H_DIM + tx * 8;
        *(float4*)(Cr + 0) = make_float4(acc[i][0], acc[i][1], acc[i][2], acc[i][3]);
        *(float4*)(Cr + 4) = make_float4(acc[i][4], acc[i][5], acc[i][6], acc[i][7]);
    }
}

// ---------------------------------------------------------------------------
extern "C" void kernel_launch(void* const* d_in, const int* in_sizes, int n_in,
                              void* d_out, int out_size)
{
    const float* hs   = (const float*)d_in[0];
    const float* cosb = (const float*)d_in[1];
    const float* sinb = (const float*)d_in[2];
    const float* wq   = (const float*)d_in[3];
    const float* wk   = (const float*)d_in[4];
    const float* wv   = (const float*)d_in[5];
    const float* wo   = (const float*)d_in[6];
    float* out = (float*)d_out;

    float *qp, *kp, *vp, *cp, *ap;
    cudaGetSymbolAddress((void**)&qp, g_q);
    cudaGetSymbolAddress((void**)&kp, g_k);
    cudaGetSymbolAddress((void**)&vp, g_v);
    cudaGetSymbolAddress((void**)&cp, g_ctx);
    cudaGetSymbolAddress((void**)&ap, g_attn);

    // attn output lives in d_out after `out` if the harness expects the tuple
    const size_t need = (size_t)S_LEN * D_MODEL + (size_t)N_H * S_LEN * S_LEN;
    float* attnBuf = ((size_t)out_size >= need) ? (out + (size_t)S_LEN * D_MODEL) : ap;

    // 1) projections
    gemm_nt_kernel<<<dim3(D_MODEL / 128, S_LEN / 128), 256>>>(hs, wq, qp, S_LEN, D_MODEL, D_MODEL);
    gemm_nt_kernel<<<dim3((N_KV * H_DIM) / 128, S_LEN / 128), 256>>>(hs, wk, kp, S_LEN, N_KV * H_DIM, D_MODEL);
    gemm_nt_kernel<<<dim3((N_KV * H_DIM) / 128, S_LEN / 128), 256>>>(hs, wv, vp, S_LEN, N_KV * H_DIM, D_MODEL);

    // 2) RoPE
    {
        int totQ = S_LEN * N_H * (H_DIM / 2);
        int totK = S_LEN * N_KV * (H_DIM / 2);
        rope_kernel<<<(totQ + 255) / 256, 256>>>(qp, cosb, sinb, N_H);
        rope_kernel<<<(totK + 255) / 256, 256>>>(kp, cosb, sinb, N_KV);
    }

    // 3) causal scores -> attn buffer
    scores_kernel<<<dim3(S_LEN / 128, S_LEN / 128, N_H), 256>>>(attnBuf);

    // 4) entmax in place (also zeros the masked upper triangle)
    entmax_kernel<<<N_H * S_LEN, 256>>>(attnBuf);

    // 5) attn @ v -> ctx
    av_kernel<<<dim3(1, S_LEN / 128, N_H), 256>>>(attnBuf);

    // 6) out = ctx @ wo^T
    gemm_nt_kernel<<<dim3(D_MODEL / 128, S_LEN / 128), 256>>>(cp, wo, out, S_LEN, D_MODEL, D_MODEL);
}